// round 15
// baseline (speedup 1.0000x reference)
#include <cuda_runtime.h>
#include <cuda_fp16.h>
#include <cstdint>

#define SEQ     512
#define INP     5
#define HID     64
#define NB      56          // batch cols per CTA
#define NTL     7           // n-tiles (8 cols each)
#define KT16    4           // full k16 tiles (k=0..63)
#define BPAD    88          // fp16 per B column (44 words = 12 mod 32: conflict-free)
#define THREADS 256

struct SmemT {
    __align__(16) __half B[2][NB * BPAD];  // [parity][col][k] -- single fp16 buffer
};

__device__ __forceinline__ uint32_t pack_h2(__half lo, __half hi) {
    __half2 t = __halves2half2(lo, hi);    // .x = lo (lower 16 bits) = smaller k
    return *(uint32_t*)&t;
}

// Paired fp16 hardware tanh (sm_75+): ONE MUFU op for two lanes
__device__ __forceinline__ __half2 tanh2(__half2 x) {
    __half2 y;
    asm("tanh.approx.f16x2 %0, %1;"
        : "=r"(*(uint32_t*)&y) : "r"(*(uint32_t*)&x));
    return y;
}

// mma.sync m16n8k16 row.col fp16 -> f32, D += A*B
__device__ __forceinline__ void mma16816(float* c, const uint32_t* a, const uint32_t* b) {
    asm volatile(
        "mma.sync.aligned.m16n8k16.row.col.f32.f16.f16.f32 "
        "{%0,%1,%2,%3}, {%4,%5,%6,%7}, {%8,%9}, {%0,%1,%2,%3};"
        : "+f"(c[0]), "+f"(c[1]), "+f"(c[2]), "+f"(c[3])
        : "r"(a[0]), "r"(a[1]), "r"(a[2]), "r"(a[3]), "r"(b[0]), "r"(b[1]));
}
// mma.sync m16n8k8 row.col fp16 -> f32, D += A*B (K-tail tile)
__device__ __forceinline__ void mma1688(float* c, const uint32_t* a, uint32_t b) {
    asm volatile(
        "mma.sync.aligned.m16n8k8.row.col.f32.f16.f16.f32 "
        "{%0,%1,%2,%3}, {%4,%5}, {%6}, {%0,%1,%2,%3};"
        : "+f"(c[0]), "+f"(c[1]), "+f"(c[2]), "+f"(c[3])
        : "r"(a[0]), "r"(a[1]), "r"(b));
}

// Extended weight matrix element: W_ext[m][k], m permuted so that within a
// warp's m-pair (tiles 2w, 2w+1) each thread's 4 C rows = i,f,g,o of one j.
//   j = (m>>5)*8 + (m&7),  g = 2*((m>>4)&1) + ((m>>3)&1)
__device__ float wext(const float* W_hh, const float* W_ih,
                      const float* b_ih, const float* b_hh, int m, int k) {
    int j   = ((m >> 5) << 3) | (m & 7);
    int g   = (((m >> 4) & 1) << 1) | ((m >> 3) & 1);
    int row = g * HID + j;
    if (k < HID)            return W_hh[row * HID + k];
    if (k < HID + INP)      return W_ih[row * INP + (k - HID)];
    if (k == HID + INP)     return b_ih[row] + b_hh[row];   // bias column
    return 0.f;
}

// ---------------------------------------------------------------------------
// HMMA LSTM (verified R14 structure). Single delta vs R14: epilogue
// activations use tanh.approx.f16x2 -- the two cells of each tile pair their
// gates into half2, so 5 MUFU ops retire 2 cells (was 10). MUFU demand drops
// from 1120 to 560 cyc/SMSP/step, back below the 1008-cyc tensor floor.
// Cell state c stays fp32 (recurrence carrier unquantized).
// ---------------------------------------------------------------------------
__global__ void __launch_bounds__(THREADS, 1)
lstm_hmma_kernel(const float* __restrict__ inputs,  // [B, SEQ, INP]
                 const float* __restrict__ W_ih,    // [256, INP]
                 const float* __restrict__ W_hh,    // [256, HID]
                 const float* __restrict__ b_ih,    // [256]
                 const float* __restrict__ b_hh,    // [256]
                 const float* __restrict__ fc_w,    // [1, HID]
                 const float* __restrict__ fc_b,    // [1]
                 float* __restrict__ out,           // [B, 1]
                 int batch)
{
    __shared__ SmemT sm;

    const int t    = threadIdx.x;
    const int lane = t & 31;
    const int w    = t >> 5;
    const int gid  = lane >> 2;          // fragment row group 0..7
    const int tig  = lane & 3;           // fragment col group 0..3
    const int jm   = (w << 3) | gid;     // this thread's hidden index
    const int batch0 = blockIdx.x * NB;

    // ---- init smem: zero both buffers, set bias row (k=69) = 1.0
    for (int idx = t; idx < 2 * NB * BPAD / 2; idx += THREADS)
        ((uint32_t*)sm.B)[idx] = 0u;
    __syncthreads();
    if (t < NB) {
        sm.B[0][t * BPAD + HID + INP] = __float2half(1.0f);
        sm.B[1][t * BPAD + HID + INP] = __float2half(1.0f);
    }

    // x(0) into parity-0 buffer rows 64..68
    for (int q = t; q < NB * INP; q += THREADS) {
        int col = q / INP, i = q - col * INP;
        int row = min(batch0 + col, batch - 1);
        sm.B[0][col * BPAD + HID + i] =
            __float2half(inputs[(size_t)row * (SEQ * INP) + i]);
    }

    // ---- load W_ext fragments into registers (single fp16), one-time
    uint32_t ahi[2][KT16][4];   // k16 tiles, k=0..63
    uint32_t ahi8[2][2];        // k8 tail, k=64..71
#pragma unroll
    for (int mt = 0; mt < 2; ++mt) {
        const int mbase = ((w << 1) | mt) << 4;
#pragma unroll
        for (int kt = 0; kt < KT16; ++kt) {
#pragma unroll
            for (int cp = 0; cp < 2; ++cp) {          // col pair: k+0/1 or k+8/9
#pragma unroll
                for (int rr = 0; rr < 2; ++rr) {      // row gid or gid+8
                    int m  = mbase + gid + rr * 8;
                    int k0 = kt * 16 + 2 * tig + cp * 8;
                    __half h0 = __float2half(wext(W_hh, W_ih, b_ih, b_hh, m, k0));
                    __half h1 = __float2half(wext(W_hh, W_ih, b_ih, b_hh, m, k0 + 1));
                    ahi[mt][kt][cp * 2 + rr] = pack_h2(h0, h1);
                }
            }
        }
        // k8 tail: k = 64 + 2*tig (+1)
#pragma unroll
        for (int rr = 0; rr < 2; ++rr) {
            int m  = mbase + gid + rr * 8;
            int k0 = 64 + 2 * tig;
            __half h0 = __float2half(wext(W_hh, W_ih, b_ih, b_hh, m, k0));
            __half h1 = __float2half(wext(W_hh, W_ih, b_ih, b_hh, m, k0 + 1));
            ahi8[mt][rr] = pack_h2(h0, h1);
        }
    }

    // x prefetch ownership: indices t and t+256 (< NB*INP = 280)
    const int  q1   = t + THREADS;
    const bool hq1  = q1 < NB * INP;
    const int  c0i  = t / INP,  i0 = t - c0i * INP;
    const int  c1i  = hq1 ? q1 / INP : 0, i1 = hq1 ? q1 - c1i * INP : 0;
    const float* xp0 = inputs + (size_t)min(batch0 + c0i, batch - 1) * (SEQ * INP) + i0;
    const float* xp1 = inputs + (size_t)min(batch0 + c1i, batch - 1) * (SEQ * INP) + i1;

    float cst[2 * NTL];
#pragma unroll
    for (int q = 0; q < 2 * NTL; ++q) cst[q] = 0.f;

    __syncthreads();

    for (int s = 0; s < SEQ; ++s) {
        // prefetch next x
        float xv0 = 0.f, xv1 = 0.f;
        const bool dox = (s + 1 < SEQ);
        if (dox) {
            xv0 = __ldg(xp0 + (size_t)(s + 1) * INP);
            if (hq1) xv1 = __ldg(xp1 + (size_t)(s + 1) * INP);
        }

        const __half* BH = sm.B[s & 1];
        __half*       WB = sm.B[(s + 1) & 1];

        float cacc[2][NTL][4];

        // B fragments, double-buffered across n-tiles
        uint32_t bh[2][KT16][2], b8h[2];

#define LOADFRAG(buf, nt)                                                     \
        {                                                                     \
            const int ncol = (nt) * 8 + gid;                                  \
            const uint32_t* colH = (const uint32_t*)(BH + ncol * BPAD);       \
            _Pragma("unroll")                                                 \
            for (int kt = 0; kt < KT16; ++kt) {                               \
                bh[buf][kt][0] = colH[kt * 8 + tig];                          \
                bh[buf][kt][1] = colH[kt * 8 + tig + 4];                      \
            }                                                                 \
            b8h[buf] = colH[32 + tig];                                        \
        }

        // Epilogue for one n-tile: BOTH cells (q=0,1) retired together.
        // Gate pairs packed into half2 -> 5 tanh.approx.f16x2 per 2 cells.
        // c state stays fp32.
#define EPILOGUE(nt)                                                          \
        {                                                                     \
            __half2 i2 = __floats2half2_rn(0.5f * cacc[0][nt][0],             \
                                           0.5f * cacc[0][nt][1]);            \
            __half2 f2 = __floats2half2_rn(0.5f * cacc[0][nt][2],             \
                                           0.5f * cacc[0][nt][3]);            \
            __half2 g2 = __floats2half2_rn(cacc[1][nt][0], cacc[1][nt][1]);   \
            __half2 o2 = __floats2half2_rn(0.5f * cacc[1][nt][2],             \
                                           0.5f * cacc[1][nt][3]);            \
            i2 = tanh2(i2); f2 = tanh2(f2); g2 = tanh2(g2); o2 = tanh2(o2);   \
            float2 iF = __half22float2(i2);                                   \
            float2 fF = __half22float2(f2);                                   \
            float2 gF = __half22float2(g2);                                   \
            float2 oF = __half22float2(o2);                                   \
            const float ig0 = fmaf(iF.x, 0.5f, 0.5f);                         \
            const float ig1 = fmaf(iF.y, 0.5f, 0.5f);                         \
            const float fg0 = fmaf(fF.x, 0.5f, 0.5f);                         \
            const float fg1 = fmaf(fF.y, 0.5f, 0.5f);                         \
            const float og0 = fmaf(oF.x, 0.5f, 0.5f);                         \
            const float og1 = fmaf(oF.y, 0.5f, 0.5f);                         \
            const float cn0 = fg0 * cst[(nt) * 2 + 0] + ig0 * gF.x;           \
            const float cn1 = fg1 * cst[(nt) * 2 + 1] + ig1 * gF.y;           \
            cst[(nt) * 2 + 0] = cn0;                                          \
            cst[(nt) * 2 + 1] = cn1;                                          \
            __half2 c2 = tanh2(__floats2half2_rn(cn0, cn1));                  \
            float2 cF = __half22float2(c2);                                   \
            const int col0 = (nt) * 8 + 2 * tig;                              \
            WB[col0 * BPAD + jm]       = __float2half(og0 * cF.x);            \
            WB[(col0 + 1) * BPAD + jm] = __float2half(og1 * cF.y);            \
        }

        LOADFRAG(0, 0);
#pragma unroll
        for (int nt = 0; nt < NTL; ++nt) {
            const int cur = nt & 1, nxt = cur ^ 1;
            // pipeline: next tile's LDS issue before this tile's MMA burst
            if (nt + 1 < NTL) LOADFRAG(nxt, nt + 1);

#pragma unroll
            for (int mt = 0; mt < 2; ++mt)
#pragma unroll
                for (int q = 0; q < 4; ++q) cacc[mt][nt][q] = 0.f;

            // 1-term fp16: W*B; mt-interleaved (2 chains)
#pragma unroll
            for (int kt = 0; kt < KT16; ++kt) {
                mma16816(cacc[0][nt], ahi[0][kt], bh[cur][kt]);
                mma16816(cacc[1][nt], ahi[1][kt], bh[cur][kt]);
            }
            mma1688(cacc[0][nt], ahi8[0], b8h[cur]);
            mma1688(cacc[1][nt], ahi8[1], b8h[cur]);

            if (nt > 0) EPILOGUE(nt - 1);
        }
        EPILOGUE(NTL - 1);
#undef EPILOGUE
#undef LOADFRAG

        // stash next x into next-parity buffer
        if (dox) {
            WB[c0i * BPAD + HID + i0] = __float2half(xv0);
            if (hq1) WB[c1i * BPAD + HID + i1] = __float2half(xv1);
        }
        __syncthreads();
    }

    // ---- final FC + leaky ReLU; h(512) is in parity-0 buffer
    const __half* FH = sm.B[0];
    const float fw0 = fc_w[lane], fw1 = fc_w[lane + 32];
    const float fb  = fc_b[0];
#pragma unroll
    for (int q = 0; q < NTL; ++q) {
        const int col = w * NTL + q;
        float hA = __half2float(FH[col * BPAD + lane]);
        float hB = __half2float(FH[col * BPAD + lane + 32]);
        float p = hA * fw0 + hB * fw1;
#pragma unroll
        for (int off = 16; off > 0; off >>= 1)
            p += __shfl_xor_sync(0xffffffffu, p, off);
        if (lane == 0) {
            const int row = batch0 + col;
            if (row < batch) {
                const float v = p + fb;
                out[row] = (v >= 0.f) ? v : 0.01f * v;
            }
        }
    }
}

extern "C" void kernel_launch(void* const* d_in, const int* in_sizes, int n_in,
                              void* d_out, int out_size) {
    const float* inputs = (const float*)d_in[0];
    const float* W_ih   = (const float*)d_in[1];
    const float* W_hh   = (const float*)d_in[2];
    const float* b_ih   = (const float*)d_in[3];
    const float* b_hh   = (const float*)d_in[4];
    const float* fc_w   = (const float*)d_in[5];
    const float* fc_b   = (const float*)d_in[6];
    float*       out    = (float*)d_out;

    const int batch = in_sizes[0] / (SEQ * INP);      // 8192
    const int grid  = (batch + NB - 1) / NB;          // 147

    lstm_hmma_kernel<<<grid, THREADS>>>(inputs, W_ih, W_hh, b_ih, b_hh,
                                        fc_w, fc_b, out, batch);
}